// round 11
// baseline (speedup 1.0000x reference)
#include <cuda_runtime.h>
#include <cuda_fp16.h>
#include <cstdint>

// ---------------------------------------------------------------------------
// TR_Linear via two single-product fp16 GEMMs on the tensor pipe (portable
// PTX: mma.sync.m16n8k16.f16 / ldmatrix / cp.async).
//   Pp^T[n][i'] (1024x1024), n=(r2*16+r4)*4+h ;  C1 = x @ Pp  (K=1024)
//   Q2^T[n2][k] (1024x256),  k=r2*16+r4, n2=i0*32+i1
//   y[b, n2*4+h] = sum_k C1[b,k*4+h]*Q2[k,n2] + bias
// Precision: all operands fp16, fp32 accumulate (rel_err ~4.1e-4, calibrated).
// R11: PERSISTENT gemm2 -- 512 blocks, each processes 4 bm-tiles as one
// continuous 32-chunk stream with Q2 resident once and the cp.async ring
// never draining between tiles; per-tile epilogue in a dedicated stg region.
// ---------------------------------------------------------------------------

#define MTOT 8192

typedef __half fp16;

__device__ fp16 g_x[MTOT * 1024];
__device__ fp16 g_pp[1024 * 1024];
__device__ fp16 g_q2[1024 * 256];
__device__ fp16 g_c1[4 * MTOT * 256];   // [h][b][k2]

// ========================= PTX helpers (portable) ==========================
__device__ __forceinline__ void cp16(uint32_t dst, const void* src) {
    asm volatile("cp.async.cg.shared.global [%0], [%1], 16;" :: "r"(dst), "l"(src));
}
#define CP_COMMIT() asm volatile("cp.async.commit_group;" ::: "memory")
#define CP_WAIT(N)  asm volatile("cp.async.wait_group %0;" :: "n"(N) : "memory")

__device__ __forceinline__ void ldm4(uint32_t& r0, uint32_t& r1, uint32_t& r2, uint32_t& r3,
                                     uint32_t addr) {
    asm volatile("ldmatrix.sync.aligned.m8n8.x4.shared.b16 {%0,%1,%2,%3}, [%4];"
                 : "=r"(r0), "=r"(r1), "=r"(r2), "=r"(r3) : "r"(addr));
}
__device__ __forceinline__ void mma_fp16(float* d, const uint32_t* a, const uint32_t* b) {
    asm volatile("mma.sync.aligned.m16n8k16.row.col.f32.f16.f16.f32 "
                 "{%0,%1,%2,%3}, {%4,%5,%6,%7}, {%8,%9}, {%0,%1,%2,%3};"
                 : "+f"(d[0]), "+f"(d[1]), "+f"(d[2]), "+f"(d[3])
                 : "r"(a[0]), "r"(a[1]), "r"(a[2]), "r"(a[3]), "r"(b[0]), "r"(b[1]));
}
__device__ __forceinline__ uint32_t cvta_s(const void* p) {
    return (uint32_t)__cvta_generic_to_shared(p);
}

// 64B-row swizzle: row stride = 32 fp16 (64B); 16B granule c (0..3) stored at
// physical granule c ^ ((row>>1)&3). Conflict-free for ldmatrix + cp.async.
__device__ __forceinline__ uint32_t swz(int row, int c) {
    return (uint32_t)(row * 32 + ((c ^ ((row >> 1) & 3)) * 8));
}

// ========================= prepass kernels =================================
__global__ void conv_x_kernel(const float* __restrict__ x) {
    int i = (blockIdx.x * blockDim.x + threadIdx.x) * 8;
    float4 v0 = *(const float4*)(x + i);
    float4 v1 = *(const float4*)(x + i + 4);
    ushort4 h0, h1;
    h0.x = __half_as_ushort(__float2half_rn(v0.x));
    h0.y = __half_as_ushort(__float2half_rn(v0.y));
    h0.z = __half_as_ushort(__float2half_rn(v0.z));
    h0.w = __half_as_ushort(__float2half_rn(v0.w));
    h1.x = __half_as_ushort(__float2half_rn(v1.x));
    h1.y = __half_as_ushort(__float2half_rn(v1.y));
    h1.z = __half_as_ushort(__float2half_rn(v1.z));
    h1.w = __half_as_ushort(__float2half_rn(v1.w));
    *(ushort4*)(g_x + i)     = h0;
    *(ushort4*)(g_x + i + 4) = h1;
}

__global__ void build_pp_kernel(const float* __restrict__ c2, const float* __restrict__ c3) {
    int idx = blockIdx.x * blockDim.x + threadIdx.x;   // n*1024 + i'
    int n = idx >> 10, ip = idx & 1023;
    int r2 = n >> 6, r4 = (n >> 2) & 15, h = n & 3;
    int o0 = h * 16 + (ip >> 6), o1 = ip & 63;
    const float* a = c2 + (r2 * 64 + o0) * 16;
    float s = 0.f;
#pragma unroll
    for (int r3 = 0; r3 < 16; r3++) s += a[r3] * c3[(r3 * 64 + o1) * 16 + r4];
    g_pp[idx] = __float2half_rn(s);
}

__global__ void build_q2_kernel(const float* __restrict__ c0, const float* __restrict__ c1) {
    int idx = blockIdx.x * blockDim.x + threadIdx.x;   // n2*256 + k
    int n2 = idx >> 8, k = idx & 255;
    int r2 = k >> 4, r4 = k & 15;
    int i0 = n2 >> 5, i1 = n2 & 31;
    const float* a = c0 + (r4 * 32 + i0) * 16;
    float s = 0.f;
#pragma unroll
    for (int r1 = 0; r1 < 16; r1++) s += a[r1] * c1[(r1 * 32 + i1) * 16 + r2];
    g_q2[idx] = __float2half_rn(s);
}

// ========================= GEMM1: C1 = x @ Pp ==============================
// 128x128 block tile, 256 threads (8 warps, warp tile 64x32).
// K=1024 in 32 chunks of 32. 4-stage ring, swizzled 64B rows.
#define G1_SLOT   8192                       // fp16 per stage (16384 B)
#define G1_STAGES 4
#define G1_SMEM   69632                      // max(ring 65536, epilogue 67584)+pad

__global__ __launch_bounds__(256, 2) void gemm1_mma() {
    extern __shared__ char dsm[];
    fp16* sm = (fp16*)dsm;
    const int t = threadIdx.x, wid = t >> 5, lane = t & 31;
    const int bm = blockIdx.y * 128, bn = blockIdx.x * 128;
    const int wm = wid & 1, wn = wid >> 1;     // warp tile 64m x 32n

    float acc[4][4][4];
#pragma unroll
    for (int a = 0; a < 4; a++)
#pragma unroll
        for (int b = 0; b < 4; b++)
#pragma unroll
            for (int c = 0; c < 4; c++) acc[a][b][c] = 0.f;

    auto load_stage = [&](int s, int k0) {
#pragma unroll
        for (int i = 0; i < 4; i++) {
            int gi = i * 256 + t;                      // 1024 x 16B granules
            int arr = gi >> 9, rem = gi & 511, row = rem >> 2, c = rem & 3;
            const fp16* src = arr ? (g_pp + (size_t)(bn + row) * 1024 + k0 + c * 8)
                                  : (g_x  + (size_t)(bm + row) * 1024 + k0 + c * 8);
            cp16(cvta_s(sm + s * G1_SLOT + arr * 4096 + swz(row, c)), src);
        }
    };

    const int lr = lane & 15, lc = lane >> 4;

    auto compute = [&](int s) {
        uint32_t base = cvta_s(sm) + (uint32_t)(s * G1_SLOT) * 2;
#pragma unroll
        for (int kk = 0; kk < 2; kk++) {
            int kidx = kk * 2 + lc;
            uint32_t ah[4][4], bh[4][2];
#pragma unroll
            for (int mi = 0; mi < 4; mi++) {
                int row = wm * 64 + mi * 16 + lr;
                ldm4(ah[mi][0], ah[mi][1], ah[mi][2], ah[mi][3], base + swz(row, kidx) * 2);
            }
#pragma unroll
            for (int p = 0; p < 2; p++) {
                int row = wn * 32 + p * 16 + lr;
                uint32_t r0, r1, r2, r3;
                ldm4(r0, r1, r2, r3, base + 4096 * 2 + swz(row, kidx) * 2);
                bh[2 * p][0] = r0; bh[2 * p][1] = r2;
                bh[2 * p + 1][0] = r1; bh[2 * p + 1][1] = r3;
            }
#pragma unroll
            for (int mi = 0; mi < 4; mi++)
#pragma unroll
                for (int ni = 0; ni < 4; ni++)
                    mma_fp16(acc[mi][ni], ah[mi], bh[ni]);
        }
    };

#pragma unroll
    for (int s = 0; s < G1_STAGES - 1; s++) {
        load_stage(s, s * 32);
        CP_COMMIT();
    }
    for (int kc = 0; kc < 32; kc++) {
        CP_WAIT(2);
        __syncthreads();
        if (kc + 3 < 32) load_stage((kc + 3) % G1_STAGES, (kc + 3) * 32);
        CP_COMMIT();
        compute(kc % G1_STAGES);
    }

    // ---- epilogue: stage fp32 tile, then fp16 into C1[h][b][k2] ----
    CP_WAIT(0);
    __syncthreads();
    float* stg = (float*)dsm;     // [128][132] = 67584 B <= 69632
#pragma unroll
    for (int mi = 0; mi < 4; mi++)
#pragma unroll
        for (int ni = 0; ni < 4; ni++) {
            int r = wm * 64 + mi * 16 + (lane >> 2);
            int c = wn * 32 + ni * 8 + (lane & 3) * 2;
            stg[r * 132 + c]           = acc[mi][ni][0];
            stg[r * 132 + c + 1]       = acc[mi][ni][1];
            stg[(r + 8) * 132 + c]     = acc[mi][ni][2];
            stg[(r + 8) * 132 + c + 1] = acc[mi][ni][3];
        }
    __syncthreads();

    const int kb = bn >> 2;
#pragma unroll
    for (int i = 0; i < 16; i++) {
        int g = i * 256 + t;                   // 4096 groups of 4 k2
        int row = g >> 5, rem = g & 31, h = rem >> 3, kg = rem & 7;
        ushort4 vh;
        vh.x = __half_as_ushort(__float2half_rn(stg[row * 132 + (kg * 4 + 0) * 4 + h]));
        vh.y = __half_as_ushort(__float2half_rn(stg[row * 132 + (kg * 4 + 1) * 4 + h]));
        vh.z = __half_as_ushort(__float2half_rn(stg[row * 132 + (kg * 4 + 2) * 4 + h]));
        vh.w = __half_as_ushort(__float2half_rn(stg[row * 132 + (kg * 4 + 3) * 4 + h]));
        size_t o = ((size_t)h * MTOT + bm + row) * 256 + kb + kg * 4;
        *(ushort4*)(g_c1 + o) = vh;
    }
}

// ========================= GEMM2 (persistent): y = C1_h @ Q2^T + bias ======
// 512 blocks (16 bn2 x 32 m-groups), 256 threads. Each block: Q2 resident
// once (8 chunked [64][32] tiles), then 4 bm-tiles (64 rows x 64 n2 x 4h)
// as one continuous 32-chunk stream through a 3-stage A ring.
// smem bytes: ring 3x16384 @0, B 32768 @49152, stg [16][260] f32 @81920.
#define G2_ASTG  8192                       // fp16 per A stage
#define G2_BOFF  24576                      // fp16 offset of B
#define G2_STGB  81920                      // byte offset of stg
#define G2_SMEM  (G2_STGB + 16 * 260 * 4)   // 98560 B

__global__ __launch_bounds__(256, 2) void gemm2_mma(const float* __restrict__ bias,
                                                    float* __restrict__ Y) {
    extern __shared__ char dsm[];
    fp16* sm = (fp16*)dsm;
    const int t = threadIdx.x, wid = t >> 5, lane = t & 31;
    const int bm0 = blockIdx.y * 256, bn2 = blockIdx.x * 64;
    const int wh = wid >> 1, mh = wid & 1;     // warp: h = wh, rows mh*32..+31

    float acc[2][8][4];
#pragma unroll
    for (int a = 0; a < 2; a++)
#pragma unroll
        for (int b = 0; b < 8; b++)
#pragma unroll
            for (int c = 0; c < 4; c++) acc[a][b][c] = 0.f;

    auto load_B = [&]() {        // full-K Q2, chunked [kc][64][32], ONCE
#pragma unroll
        for (int i = 0; i < 8; i++) {
            int gi = i * 256 + t;                    // 2048 x 16B granules
            int kcch = gi >> 8, rem = gi & 255, row = rem >> 2, c = rem & 3;
            const fp16* src = g_q2 + (size_t)(bn2 + row) * 256 + kcch * 32 + c * 8;
            cp16(cvta_s(sm + G2_BOFF + kcch * 2048 + swz(row, c)), src);
        }
    };
    auto load_stage = [&](int s, int chunk) {
        int tile = chunk >> 3, k0 = (chunk & 7) * 32;
        int bmt = bm0 + tile * 64;
#pragma unroll
        for (int i = 0; i < 4; i++) {
            int gi = i * 256 + t;                    // 1024 x 16B granules
            int h = gi >> 8, rem = gi & 255, row = rem >> 2, c = rem & 3;
            const fp16* src = g_c1 + ((size_t)h * MTOT + bmt + row) * 256 + k0 + c * 8;
            cp16(cvta_s(sm + s * G2_ASTG + h * 2048 + swz(row, c)), src);
        }
    };

    const int lr = lane & 15, lc = lane >> 4;

    auto compute = [&](int s, int kc) {
        uint32_t abase = cvta_s(sm) + (uint32_t)(s * G2_ASTG) * 2;
        uint32_t bbase = cvta_s(sm) + (uint32_t)(G2_BOFF + kc * 2048) * 2;
#pragma unroll
        for (int kk = 0; kk < 2; kk++) {
            int kidx = kk * 2 + lc;
            uint32_t ah[2][4], bh[8][2];
#pragma unroll
            for (int mi = 0; mi < 2; mi++) {
                int row = mh * 32 + mi * 16 + lr;
                ldm4(ah[mi][0], ah[mi][1], ah[mi][2], ah[mi][3],
                     abase + ((uint32_t)(wh * 2048) + swz(row, kidx)) * 2);
            }
#pragma unroll
            for (int p = 0; p < 4; p++) {
                int row = p * 16 + lr;
                uint32_t r0, r1, r2, r3;
                ldm4(r0, r1, r2, r3, bbase + swz(row, kidx) * 2);
                bh[2 * p][0] = r0; bh[2 * p][1] = r2;
                bh[2 * p + 1][0] = r1; bh[2 * p + 1][1] = r3;
            }
#pragma unroll
            for (int mi = 0; mi < 2; mi++)
#pragma unroll
                for (int ni = 0; ni < 8; ni++)
                    mma_fp16(acc[mi][ni], ah[mi], bh[ni]);
        }
    };

    // Per-tile epilogue: 4 passes of 16 rows through dedicated stg region
    // (never touches ring stages -> the ring stays full across tiles).
    float* stg = (float*)(dsm + G2_STGB);    // [16][260]
    auto epilogue = [&](int tile) {
        int bmt = bm0 + tile * 64;
#pragma unroll
        for (int p = 0; p < 4; p++) {
            __syncthreads();
            if (mh == (p >> 1)) {
                int mi = p & 1;
#pragma unroll
                for (int ni = 0; ni < 8; ni++) {
                    int r = lane >> 2;
                    int n2l = ni * 8 + (lane & 3) * 2;
                    stg[r * 260 + n2l * 4 + wh]             = acc[mi][ni][0];
                    stg[r * 260 + (n2l + 1) * 4 + wh]       = acc[mi][ni][1];
                    stg[(r + 8) * 260 + n2l * 4 + wh]       = acc[mi][ni][2];
                    stg[(r + 8) * 260 + (n2l + 1) * 4 + wh] = acc[mi][ni][3];
                }
            }
            __syncthreads();
#pragma unroll
            for (int i = 0; i < 4; i++) {
                int g = i * 256 + t;                 // 1024 float4 groups
                int r = g >> 6, c4 = (g & 63) * 4;
                float4 v = *(const float4*)&stg[r * 260 + c4];
                float4 bz = *(const float4*)(bias + bn2 * 4 + c4);
                v.x += bz.x; v.y += bz.y; v.z += bz.z; v.w += bz.w;
                *(float4*)(Y + (size_t)(bmt + p * 16 + r) * 4096 + bn2 * 4 + c4) = v;
            }
        }
        // reset accumulators for the next tile
#pragma unroll
        for (int a = 0; a < 2; a++)
#pragma unroll
            for (int b = 0; b < 8; b++)
#pragma unroll
                for (int c = 0; c < 4; c++) acc[a][b][c] = 0.f;
    };

    load_B();
    load_stage(0, 0);
    CP_COMMIT();                 // group 0: B + chunk0
    load_stage(1, 1);
    CP_COMMIT();                 // group 1: chunk1
    for (int c = 0; c < 32; c++) {
        CP_WAIT(1);
        __syncthreads();
        if (c + 2 < 32) load_stage((c + 2) % 3, c + 2);
        CP_COMMIT();
        compute(c % 3, c & 7);
        if ((c & 7) == 7) epilogue(c >> 3);
    }
}

// ========================= launch ==========================================
extern "C" void kernel_launch(void* const* d_in, const int* in_sizes, int n_in,
                              void* d_out, int out_size) {
    const float* x     = (const float*)d_in[0];
    const float* core0 = (const float*)d_in[1];
    const float* core1 = (const float*)d_in[2];
    const float* core2 = (const float*)d_in[3];
    const float* core3 = (const float*)d_in[4];
    const float* bias  = (const float*)d_in[5];
    float* y = (float*)d_out;

    cudaFuncSetAttribute(gemm1_mma, cudaFuncAttributeMaxDynamicSharedMemorySize, G1_SMEM);
    cudaFuncSetAttribute(gemm2_mma, cudaFuncAttributeMaxDynamicSharedMemorySize, G2_SMEM);

    conv_x_kernel<<<(MTOT * 1024) / (256 * 8), 256>>>(x);
    build_pp_kernel<<<(1024 * 1024) / 256, 256>>>(core2, core3);
    build_q2_kernel<<<(1024 * 256) / 256, 256>>>(core0, core1);

    gemm1_mma<<<dim3(8, 64), 256, G1_SMEM>>>();
    gemm2_mma<<<dim3(16, 32), 256, G2_SMEM>>>(bias, y);
}